// round 5
// baseline (speedup 1.0000x reference)
#include <cuda_runtime.h>

// memoryClusterer: superpixel gather + per-class contrast maps.
//   d_in[0] spx       int32 [1,1,1080,1920]
//   d_in[1] knn_pred  int32 [2000]
//   d_in[2] knn_dist  f32   [2000,8]
//   d_in[3] cent_dist f32   [2000,8]
//   out (f32): [preseg (HW)] ++ [attmaps (7,4,H,W)]
//     plane (a,k): a=0..6 (class j=a+1); k: 0=knn_att[j], 1=knn_contrast,
//                                        2=cent_att[j], 3=cent_contrast
// contrast_j = max over channels != j = (argmax==j ? max2 : max1).
//
// R5: 4 px/thread, STG.128 everywhere (4x fewer store instrs + address math),
// smem tables (stride 20 words for bank spread), running plane pointers,
// persistent blocks. Goal: execution side faster than the DRAM write stream.

static constexpr int HW  = 1080 * 1920;     // 2,073,600 (divisible by 4)
static constexpr int NQ  = HW / 4;          // 518,400 quads
static constexpr int S   = 2000;
static constexpr int NC  = 8;
static constexpr int ROW = 20;              // smem row stride in words
static constexpr int SMEM_BYTES = S * ROW * 4;   // 160,000 B
static constexpr int NTHREADS = 1024;

__device__ __forceinline__ void max2of8(const float v[NC], float& m1, float& m2, int& arg) {
    m1 = v[0];
    m2 = __int_as_float(0xff800000);  // -inf
    arg = 0;
#pragma unroll
    for (int c = 1; c < NC; c++) {
        float x = v[c];
        if (x > m1) { m2 = m1; m1 = x; arg = c; }
        else if (x > m2) { m2 = x; }
    }
}

__global__ __launch_bounds__(NTHREADS, 1)
void memory_clusterer_kernel(const int4* __restrict__ spx4,
                             const int* __restrict__ knn_pred,
                             const float4* __restrict__ knn_dist4,
                             const float4* __restrict__ cent_dist4,
                             float* __restrict__ out) {
    extern __shared__ float s_tab[];   // [S][ROW]: 8 knn, 8 cent, pred, pad

    for (int r = threadIdx.x; r < S; r += NTHREADS) {
        float4 a = __ldg(knn_dist4 + 2 * r);
        float4 b = __ldg(knn_dist4 + 2 * r + 1);
        float4 c = __ldg(cent_dist4 + 2 * r);
        float4 d = __ldg(cent_dist4 + 2 * r + 1);
        float p = (float)__ldg(knn_pred + r);
        float* row = s_tab + r * ROW;
        *reinterpret_cast<float4*>(row)      = a;
        *reinterpret_cast<float4*>(row + 4)  = b;
        *reinterpret_cast<float4*>(row + 8)  = c;
        *reinterpret_cast<float4*>(row + 12) = d;
        row[16] = p;
    }
    __syncthreads();

    const int stride = gridDim.x * NTHREADS;
    for (int t = blockIdx.x * NTHREADS + threadIdx.x; t < NQ; t += stride) {
        const int i = t << 2;

        const int4 sp = __ldg(spx4 + t);
        const float* r0 = s_tab + (sp.x - 1) * ROW;
        const float* r1 = s_tab + (sp.y - 1) * ROW;
        const float* r2 = s_tab + (sp.z - 1) * ROW;
        const float* r3 = s_tab + (sp.w - 1) * ROW;

        // ---- preseg ----
        *reinterpret_cast<float4*>(out + i) =
            make_float4(r0[16], r1[16], r2[16], r3[16]);

        // ---- phase 1: knn planes (k = 0,1) ----
        {
            float v0[NC], v1[NC], v2[NC], v3[NC];
            *reinterpret_cast<float4*>(v0)     = *reinterpret_cast<const float4*>(r0);
            *reinterpret_cast<float4*>(v0 + 4) = *reinterpret_cast<const float4*>(r0 + 4);
            *reinterpret_cast<float4*>(v1)     = *reinterpret_cast<const float4*>(r1);
            *reinterpret_cast<float4*>(v1 + 4) = *reinterpret_cast<const float4*>(r1 + 4);
            *reinterpret_cast<float4*>(v2)     = *reinterpret_cast<const float4*>(r2);
            *reinterpret_cast<float4*>(v2 + 4) = *reinterpret_cast<const float4*>(r2 + 4);
            *reinterpret_cast<float4*>(v3)     = *reinterpret_cast<const float4*>(r3);
            *reinterpret_cast<float4*>(v3 + 4) = *reinterpret_cast<const float4*>(r3 + 4);

            float m1a, m2a, m1b, m2b, m1c, m2c, m1d, m2d;
            int aga, agb, agc, agd;
            max2of8(v0, m1a, m2a, aga);
            max2of8(v1, m1b, m2b, agb);
            max2of8(v2, m1c, m2c, agc);
            max2of8(v3, m1d, m2d, agd);

            float* p0 = out + HW + i;        // plane 4a+0
            float* p1 = p0 + HW;             // plane 4a+1
#pragma unroll
            for (int a = 0; a < 7; a++) {
                const int j = a + 1;
                *reinterpret_cast<float4*>(p0) =
                    make_float4(v0[j], v1[j], v2[j], v3[j]);
                *reinterpret_cast<float4*>(p1) =
                    make_float4(aga == j ? m2a : m1a,
                                agb == j ? m2b : m1b,
                                agc == j ? m2c : m1c,
                                agd == j ? m2d : m1d);
                p0 += (size_t)4 * HW;
                p1 += (size_t)4 * HW;
            }
        }

        // ---- phase 2: cent planes (k = 2,3) ----
        {
            float v0[NC], v1[NC], v2[NC], v3[NC];
            *reinterpret_cast<float4*>(v0)     = *reinterpret_cast<const float4*>(r0 + 8);
            *reinterpret_cast<float4*>(v0 + 4) = *reinterpret_cast<const float4*>(r0 + 12);
            *reinterpret_cast<float4*>(v1)     = *reinterpret_cast<const float4*>(r1 + 8);
            *reinterpret_cast<float4*>(v1 + 4) = *reinterpret_cast<const float4*>(r1 + 12);
            *reinterpret_cast<float4*>(v2)     = *reinterpret_cast<const float4*>(r2 + 8);
            *reinterpret_cast<float4*>(v2 + 4) = *reinterpret_cast<const float4*>(r2 + 12);
            *reinterpret_cast<float4*>(v3)     = *reinterpret_cast<const float4*>(r3 + 8);
            *reinterpret_cast<float4*>(v3 + 4) = *reinterpret_cast<const float4*>(r3 + 12);

            float m1a, m2a, m1b, m2b, m1c, m2c, m1d, m2d;
            int aga, agb, agc, agd;
            max2of8(v0, m1a, m2a, aga);
            max2of8(v1, m1b, m2b, agb);
            max2of8(v2, m1c, m2c, agc);
            max2of8(v3, m1d, m2d, agd);

            float* p2 = out + HW + i + (size_t)2 * HW;   // plane 4a+2
            float* p3 = p2 + HW;                          // plane 4a+3
#pragma unroll
            for (int a = 0; a < 7; a++) {
                const int j = a + 1;
                *reinterpret_cast<float4*>(p2) =
                    make_float4(v0[j], v1[j], v2[j], v3[j]);
                *reinterpret_cast<float4*>(p3) =
                    make_float4(aga == j ? m2a : m1a,
                                agb == j ? m2b : m1b,
                                agc == j ? m2c : m1c,
                                agd == j ? m2d : m1d);
                p2 += (size_t)4 * HW;
                p3 += (size_t)4 * HW;
            }
        }
    }
}

extern "C" void kernel_launch(void* const* d_in, const int* in_sizes, int n_in,
                              void* d_out, int out_size) {
    const int4* spx4 = (const int4*)d_in[0];
    const int* knn_pred = (const int*)d_in[1];
    const float4* knn_dist4 = (const float4*)d_in[2];
    const float4* cent_dist4 = (const float4*)d_in[3];
    float* out = (float*)d_out;

    static int n_sms = 0;
    if (n_sms == 0) {
        int dev = 0;
        cudaGetDevice(&dev);
        cudaDeviceGetAttribute(&n_sms, cudaDevAttrMultiProcessorCount, dev);
        cudaFuncSetAttribute(memory_clusterer_kernel,
                             cudaFuncAttributeMaxDynamicSharedMemorySize, SMEM_BYTES);
    }

    memory_clusterer_kernel<<<n_sms, NTHREADS, SMEM_BYTES>>>(
        spx4, knn_pred, knn_dist4, cent_dist4, out);
}